// round 6
// baseline (speedup 1.0000x reference)
#include <cuda_runtime.h>
#include <cuda_bf16.h>
#include <cstdint>

#define B_ 128
#define T_ 4096
#define F_ 64
#define H_ 128
#define G_ 512   /* 4*H */

// Scratch: precomputed input gates, PERMUTED layout:
//   g_xg[b][t][r*4 + gate] = (X[b,t,:]@W_ih^T + b_ih + b_hh)[gate*128 + r]
// so lstm thread t (r=t>>2, gate=t&3) reads element t -> fully coalesced.
__device__ float g_xg[268435456ull];   // 1 GiB

// ---------------- f32x2 helpers (packed fp32: 2x FFMA throughput) ----------
__device__ __forceinline__ unsigned long long packf2(float x, float y) {
    unsigned long long r;
    asm("mov.b64 %0, {%1, %2};" : "=l"(r) : "f"(x), "f"(y));
    return r;
}
__device__ __forceinline__ float2 unpackf2(unsigned long long v) {
    float2 r;
    asm("mov.b64 {%0, %1}, %2;" : "=f"(r.x), "=f"(r.y) : "l"(v));
    return r;
}
__device__ __forceinline__ unsigned long long ffma2(unsigned long long a,
                                                    unsigned long long b,
                                                    unsigned long long c) {
    unsigned long long d;
    asm("fma.rn.f32x2 %0, %1, %2, %3;" : "=l"(d) : "l"(a), "l"(b), "l"(c));
    return d;
}

__device__ __forceinline__ float sigmoidf_(float x) {
    return __fdividef(1.0f, 1.0f + __expf(-x));
}
__device__ __forceinline__ float tanhf_(float x) {
    float ax = fabsf(x);
    float e  = __expf(-2.0f * ax);           // e in (0,1], never overflows
    float t  = __fdividef(1.0f - e, 1.0f + e);
    return copysignf(t, x);
}

// ---------------------------------------------------------------------------
// Kernel 1: xg (input-gate precompute), writes permuted layout.
// grid (T/64, B), 256 threads. Thread t computes output positions t and t+256,
// which correspond to original gate rows jA=(t&3)*128+(t>>2) and jA+64.
// ---------------------------------------------------------------------------
__global__ __launch_bounds__(256) void xg_kernel(
    const float* __restrict__ X,
    const float* __restrict__ W_ih,
    const float* __restrict__ b_ih,
    const float* __restrict__ b_hh)
{
    extern __shared__ float smem[];
    float* sW = smem;                 // 512 x 65 (pad 1 -> conflict-free)
    float* sX = smem + 512 * 65;      // 64 x 64 (16B-aligned offset)

    const int t  = threadIdx.x;
    const int b  = blockIdx.y;
    const int t0 = blockIdx.x * 64;

    for (int idx = t; idx < 512 * 64; idx += 256) {
        int j = idx >> 6, k = idx & 63;
        sW[j * 65 + k] = W_ih[idx];
    }
    const float* Xb = X + ((size_t)b * T_ + t0) * F_;
    for (int idx = t; idx < 64 * 64; idx += 256) sX[idx] = Xb[idx];
    __syncthreads();

    // original gate-row indices for permuted output columns t and t+256
    const int jA = (t & 3) * 128 + (t >> 2);
    const int jB = jA + 64;

    unsigned long long wpA[32], wpB[32];
#pragma unroll
    for (int p = 0; p < 32; ++p) {
        wpA[p] = packf2(sW[jA * 65 + 2 * p], sW[jA * 65 + 2 * p + 1]);
        wpB[p] = packf2(sW[jB * 65 + 2 * p], sW[jB * 65 + 2 * p + 1]);
    }
    const float biasA = __ldg(b_ih + jA) + __ldg(b_hh + jA);
    const float biasB = __ldg(b_ih + jB) + __ldg(b_hh + jB);

    float* outb = g_xg + ((size_t)b * T_ + t0) * G_;

    for (int tt = 0; tt < 64; ++tt) {
        const ulonglong2* x2 = (const ulonglong2*)(sX + tt * 64);
        unsigned long long aA0 = 0, aA1 = 0, aB0 = 0, aB1 = 0;
#pragma unroll
        for (int q = 0; q < 16; ++q) {
            ulonglong2 hq = x2[q];            // 4 floats, broadcast LDS.128
            aA0 = ffma2(wpA[2 * q],     hq.x, aA0);
            aA1 = ffma2(wpA[2 * q + 1], hq.y, aA1);
            aB0 = ffma2(wpB[2 * q],     hq.x, aB0);
            aB1 = ffma2(wpB[2 * q + 1], hq.y, aB1);
        }
        float2 u0 = unpackf2(aA0), u1 = unpackf2(aA1);
        float2 v0 = unpackf2(aB0), v1 = unpackf2(aB1);
        outb[(size_t)tt * G_ + t]       = (u0.x + u0.y) + (u1.x + u1.y) + biasA;
        outb[(size_t)tt * G_ + t + 256] = (v0.x + v0.y) + (v1.x + v1.y) + biasB;
    }
}

// ---------------------------------------------------------------------------
// Kernel 2: persistent recurrent LSTM. One CTA per batch row, 512 threads
// (16 warps -> 4/SMSP). Thread t owns ONE gate row: r = t>>2, gate = t&3
// (0=i,1=f,2=g,3=o), W_hh row gate*128+r fully register-resident in fp32
// (64 u64 regs). All 4 gates of hidden unit r are lanes 4q..4q+3 of a warp:
// the c/h update runs on the f-lane via 3 intra-quad shuffles.
// One __syncthreads per step (h double-buffered in shared).
// ---------------------------------------------------------------------------
__global__ __launch_bounds__(512, 1) void lstm_kernel(
    const float* __restrict__ W_hh,
    float* __restrict__ out)
{
    __shared__ alignas(16) float sh_h[2][128];

    const int t    = threadIdx.x;
    const int b    = blockIdx.x;
    const int r    = t >> 2;
    const int gate = t & 3;
    const unsigned lane = t & 31;
    const unsigned qbase = lane & ~3u;

    const float* W = W_hh + (size_t)(gate * 128 + r) * H_;

    // Full weight row in registers as 64 f32x2 pairs
    unsigned long long wp[64];
#pragma unroll
    for (int q = 0; q < 32; ++q) {
        float4 a = __ldg((const float4*)(W + 4 * q));
        wp[2 * q]     = packf2(a.x, a.y);
        wp[2 * q + 1] = packf2(a.z, a.w);
    }

    if (t < 256) ((float*)sh_h)[t] = 0.0f;    // zero both h buffers
    __syncthreads();

    const float* px = g_xg + (size_t)b * T_ * G_ + t;   // permuted, coalesced
    float xg0 = __ldg(px);

    float c = 0.0f;
    float h_out = 0.0f;

    for (int ts = 0; ts < T_; ++ts) {
        const int inc = (ts < T_ - 1) ? G_ : 0;
        float nx = __ldg(px + inc);                      // next-step prefetch

        const ulonglong2* hv = (const ulonglong2*)sh_h[ts & 1];
        unsigned long long a0 = 0, a1 = 0;
#pragma unroll
        for (int q = 0; q < 32; ++q) {
            ulonglong2 hq = hv[q];                       // broadcast LDS.128
            a0 = ffma2(wp[2 * q],     hq.x, a0);
            a1 = ffma2(wp[2 * q + 1], hq.y, a1);
        }
        float2 u0 = unpackf2(a0), u1 = unpackf2(a1);
        float gv = (u0.x + u0.y) + (u1.x + u1.y) + xg0;

        // gate 2 (g) -> tanh, others -> sigmoid
        float act = (gate == 2) ? tanhf_(gv) : sigmoidf_(gv);

        // quad exchange: f-lane gathers i, g, o
        float iv = __shfl_sync(0xFFFFFFFFu, act, qbase);
        float gg = __shfl_sync(0xFFFFFFFFu, act, qbase | 2u);
        float ov = __shfl_sync(0xFFFFFFFFu, act, qbase | 3u);
        if (gate == 1) {                                 // act = sigmoid(f)
            c = fmaf(act, c, iv * gg);                   // c = f*c + i*g
            float h = ov * tanhf_(c);                    // h = o*tanh(c)
            sh_h[(ts + 1) & 1][r] = h;
            h_out = h;
        }

        xg0 = nx; px += inc;
        __syncthreads();                                 // h visible next step
    }

    if (gate == 1) out[(size_t)b * H_ + r] = h_out;
}

// ---------------------------------------------------------------------------
extern "C" void kernel_launch(void* const* d_in, const int* in_sizes, int n_in,
                              void* d_out, int out_size)
{
    const float* X    = (const float*)d_in[0];   // [128,4096,64]
    const float* W_ih = (const float*)d_in[1];   // [512,64]
    const float* W_hh = (const float*)d_in[2];   // [512,128]
    const float* b_ih = (const float*)d_in[3];   // [512]
    const float* b_hh = (const float*)d_in[4];   // [512]
    float* out = (float*)d_out;                  // [128,128]

    size_t smem1 = (size_t)(512 * 65 + 64 * 64) * sizeof(float);  // ~146 KB
    cudaFuncSetAttribute(xg_kernel,
                         cudaFuncAttributeMaxDynamicSharedMemorySize, (int)smem1);

    dim3 g1(T_ / 64, B_);
    xg_kernel<<<g1, 256, smem1>>>(X, W_ih, b_ih, b_hh);
    lstm_kernel<<<B_, 512>>>(W_hh, out);
}

// round 7
// speedup vs baseline: 1.7381x; 1.7381x over previous
#include <cuda_runtime.h>
#include <cuda_bf16.h>
#include <cstdint>

#define B_ 128
#define T_ 4096
#define F_ 64
#define H_ 128
#define G_ 512   /* 4*H */

// Scratch: precomputed input gates, PERMUTED layout:
//   g_xg[b][t][r*4 + gate] = (X[b,t,:]@W_ih^T + b_ih + b_hh)[gate*128 + r]
// lstm thread t (r=t>>2, gate=t&3) reads element t -> fully coalesced.
__device__ float g_xg[268435456ull];   // 1 GiB

// ---------------- f32x2 helpers (packed fp32: 2x FFMA throughput) ----------
__device__ __forceinline__ unsigned long long packf2(float x, float y) {
    unsigned long long r;
    asm("mov.b64 %0, {%1, %2};" : "=l"(r) : "f"(x), "f"(y));
    return r;
}
__device__ __forceinline__ float2 unpackf2(unsigned long long v) {
    float2 r;
    asm("mov.b64 {%0, %1}, %2;" : "=f"(r.x), "=f"(r.y) : "l"(v));
    return r;
}
__device__ __forceinline__ unsigned long long ffma2(unsigned long long a,
                                                    unsigned long long b,
                                                    unsigned long long c) {
    unsigned long long d;
    asm("fma.rn.f32x2 %0, %1, %2, %3;" : "=l"(d) : "l"(a), "l"(b), "l"(c));
    return d;
}

__device__ __forceinline__ float sigmoidf_(float x) {
    return __fdividef(1.0f, 1.0f + __expf(-x));
}
__device__ __forceinline__ float tanhf_(float x) {
    float ax = fabsf(x);
    float e  = __expf(-2.0f * ax);           // e in (0,1], never overflows
    float t  = __fdividef(1.0f - e, 1.0f + e);
    return copysignf(t, x);
}

// ---------------------------------------------------------------------------
// Kernel 1: xg (input-gate precompute), writes permuted layout.
// grid (T/64, B), 256 threads. Thread t computes output positions t and t+256,
// corresponding to original gate rows jA=(t&3)*128+(t>>2) and jA+64.
// ---------------------------------------------------------------------------
__global__ __launch_bounds__(256) void xg_kernel(
    const float* __restrict__ X,
    const float* __restrict__ W_ih,
    const float* __restrict__ b_ih,
    const float* __restrict__ b_hh)
{
    extern __shared__ float smem[];
    float* sW = smem;                 // 512 x 65 (pad 1 -> conflict-free)
    float* sX = smem + 512 * 65;      // 64 x 64 (16B-aligned offset)

    const int t  = threadIdx.x;
    const int b  = blockIdx.y;
    const int t0 = blockIdx.x * 64;

    for (int idx = t; idx < 512 * 64; idx += 256) {
        int j = idx >> 6, k = idx & 63;
        sW[j * 65 + k] = W_ih[idx];
    }
    const float* Xb = X + ((size_t)b * T_ + t0) * F_;
    for (int idx = t; idx < 64 * 64; idx += 256) sX[idx] = Xb[idx];
    __syncthreads();

    const int jA = (t & 3) * 128 + (t >> 2);
    const int jB = jA + 64;

    unsigned long long wpA[32], wpB[32];
#pragma unroll
    for (int p = 0; p < 32; ++p) {
        wpA[p] = packf2(sW[jA * 65 + 2 * p], sW[jA * 65 + 2 * p + 1]);
        wpB[p] = packf2(sW[jB * 65 + 2 * p], sW[jB * 65 + 2 * p + 1]);
    }
    const float biasA = __ldg(b_ih + jA) + __ldg(b_hh + jA);
    const float biasB = __ldg(b_ih + jB) + __ldg(b_hh + jB);

    float* outb = g_xg + ((size_t)b * T_ + t0) * G_;

    for (int tt = 0; tt < 64; ++tt) {
        const ulonglong2* x2 = (const ulonglong2*)(sX + tt * 64);
        unsigned long long aA0 = 0, aA1 = 0, aB0 = 0, aB1 = 0;
#pragma unroll
        for (int q = 0; q < 16; ++q) {
            ulonglong2 hq = x2[q];            // 4 floats, broadcast LDS.128
            aA0 = ffma2(wpA[2 * q],     hq.x, aA0);
            aA1 = ffma2(wpA[2 * q + 1], hq.y, aA1);
            aB0 = ffma2(wpB[2 * q],     hq.x, aB0);
            aB1 = ffma2(wpB[2 * q + 1], hq.y, aB1);
        }
        float2 u0 = unpackf2(aA0), u1 = unpackf2(aA1);
        float2 v0 = unpackf2(aB0), v1 = unpackf2(aB1);
        outb[(size_t)tt * G_ + t]       = (u0.x + u0.y) + (u1.x + u1.y) + biasA;
        outb[(size_t)tt * G_ + t + 256] = (v0.x + v0.y) + (v1.x + v1.y) + biasB;
    }
}

// ---------------------------------------------------------------------------
// Kernel 2: persistent recurrent LSTM. One CTA per batch row, 512 threads
// (16 warps, 4/SMSP). Thread t owns ONE gate row: r=t>>2, gate=t&3
// (0=i,1=f,2=g,3=o). Weight row split to fit the 128-reg/thread cap:
//   k = 0..95  : fp32 register-resident (48 u64 pairs = 96 regs)
//   k = 96..127: fp32 streamed from shared each step (8 KB/warp-set,
//                64 KB/CTA/step = 512 crossbar cyc, overlaps the FMA pipe)
// All 4 gates of unit r are adjacent lanes: c/h epilogue via 3 quad shuffles.
// One __syncthreads per step; h double-buffered in shared.
// ---------------------------------------------------------------------------
__global__ __launch_bounds__(512, 1) void lstm_kernel(
    const float* __restrict__ W_hh,
    float* __restrict__ out)
{
    extern __shared__ float dsm[];
    float* sh_h = dsm;                                // [2][128]
    ulonglong2* sws = (ulonglong2*)(dsm + 256);       // [8][512], 64 KB

    const int t    = threadIdx.x;
    const int b    = blockIdx.x;
    const int r    = t >> 2;
    const int gate = t & 3;
    const unsigned lane  = t & 31;
    const unsigned qbase = lane & ~3u;

    const float* W = W_hh + (size_t)(gate * 128 + r) * H_;

    // k = 0..95 resident as 48 f32x2 pairs (96 regs)
    unsigned long long wp[48];
#pragma unroll
    for (int q = 0; q < 24; ++q) {
        float4 a = __ldg((const float4*)(W + 4 * q));
        wp[2 * q]     = packf2(a.x, a.y);
        wp[2 * q + 1] = packf2(a.z, a.w);
    }
    // k = 96..127 into shared, lane-major (conflict-free streaming)
#pragma unroll
    for (int v = 0; v < 8; ++v) {
        float4 a = __ldg((const float4*)(W + 96 + 4 * v));
        sws[v * 512 + t] = *(const ulonglong2*)&a;
    }
    if (t < 256) sh_h[t] = 0.0f;                      // zero both h buffers
    __syncthreads();

    const float* px = g_xg + (size_t)b * T_ * G_ + t; // permuted, coalesced
    float xg0 = __ldg(px);

    float c = 0.0f;
    float h_out = 0.0f;

    for (int ts = 0; ts < T_; ++ts) {
        const int inc = (ts < T_ - 1) ? G_ : 0;
        float nx = __ldg(px + inc);                   // next-step xg prefetch

        const ulonglong2* hv = (const ulonglong2*)(sh_h + ((ts & 1) << 7));
        unsigned long long a0 = 0, a1 = 0;
#pragma unroll
        for (int q = 0; q < 24; ++q) {                // k=0..95, resident W
            ulonglong2 hq = hv[q];                    // broadcast LDS.128
            a0 = ffma2(wp[2 * q],     hq.x, a0);
            a1 = ffma2(wp[2 * q + 1], hq.y, a1);
        }
#pragma unroll
        for (int v = 0; v < 8; ++v) {                 // k=96..127, streamed W
            ulonglong2 hq = hv[24 + v];
            ulonglong2 wv = sws[v * 512 + t];
            a0 = ffma2(wv.x, hq.x, a0);
            a1 = ffma2(wv.y, hq.y, a1);
        }
        float2 u0 = unpackf2(a0), u1 = unpackf2(a1);
        float gv = (u0.x + u0.y) + (u1.x + u1.y) + xg0;

        // gate 2 (g) -> tanh, others -> sigmoid
        float act = (gate == 2) ? tanhf_(gv) : sigmoidf_(gv);

        // quad exchange: f-lane gathers i, g, o
        float iv = __shfl_sync(0xFFFFFFFFu, act, qbase);
        float gg = __shfl_sync(0xFFFFFFFFu, act, qbase | 2u);
        float ov = __shfl_sync(0xFFFFFFFFu, act, qbase | 3u);
        if (gate == 1) {                              // act = sigmoid(f)
            c = fmaf(act, c, iv * gg);                // c = f*c + i*g
            float h = ov * tanhf_(c);                 // h = o*tanh(c)
            sh_h[(((ts + 1) & 1) << 7) + r] = h;
            h_out = h;
        }

        xg0 = nx; px += inc;
        __syncthreads();                              // h visible next step
    }

    if (gate == 1) out[(size_t)b * H_ + r] = h_out;
}

// ---------------------------------------------------------------------------
extern "C" void kernel_launch(void* const* d_in, const int* in_sizes, int n_in,
                              void* d_out, int out_size)
{
    const float* X    = (const float*)d_in[0];   // [128,4096,64]
    const float* W_ih = (const float*)d_in[1];   // [512,64]
    const float* W_hh = (const float*)d_in[2];   // [512,128]
    const float* b_ih = (const float*)d_in[3];   // [512]
    const float* b_hh = (const float*)d_in[4];   // [512]
    float* out = (float*)d_out;                  // [128,128]

    size_t smem1 = (size_t)(512 * 65 + 64 * 64) * sizeof(float);  // ~146 KB
    cudaFuncSetAttribute(xg_kernel,
                         cudaFuncAttributeMaxDynamicSharedMemorySize, (int)smem1);

    size_t smem2 = 256 * sizeof(float) + 8 * 512 * sizeof(ulonglong2); // 66.5 KB
    cudaFuncSetAttribute(lstm_kernel,
                         cudaFuncAttributeMaxDynamicSharedMemorySize, (int)smem2);

    dim3 g1(T_ / 64, B_);
    xg_kernel<<<g1, 256, smem1>>>(X, W_ih, b_ih, b_hh);
    lstm_kernel<<<B_, 512, smem2>>>(W_hh, out);
}